// round 12
// baseline (speedup 1.0000x reference)
#include <cuda_runtime.h>
#include <cuda_fp16.h>
#include <stdint.h>

#define NB 8
#define NH 16
#define NS 1024
#define ND 128

// CTA: 4 warps, 64 q-rows, 64-key k-tiles.
// smem: Q hi/lo (persistent) + K hi/lo + V hi fp16 tiles (256B rows, XOR-swizzled)
#define SM_QH 0
#define SM_QL 16384
#define SM_KH 32768
#define SM_KL 49152
#define SM_VH 65536
#define SMEM_TOTAL 81920

#define DEVFN static __device__ __forceinline__

DEVFN uint32_t smem_u32(const void* p){
  uint32_t a;
  asm("{.reg .u64 t; cvta.to.shared.u64 t,%1; cvt.u32.u64 %0,t;}":"=r"(a):"l"(p));
  return a;
}
DEVFN uint32_t swz(int r, int c){
  return (uint32_t)(r*256 + ((((c>>3) ^ (r&7)) & 15) << 4) + (c&7)*2);
}
DEVFN float f16rt(float x){ return __half2float(__float2half_rn(x)); }
DEVFN uint32_t pkh(float lo, float hi){
  uint32_t r; asm("cvt.rn.f16x2.f32 %0,%1,%2;":"=r"(r):"f"(hi),"f"(lo)); return r;
}
DEVFN void pref(const void* p){ asm volatile("prefetch.global.L2 [%0];"::"l"(p)); }
DEVFN void ldsm4(uint32_t* r, uint32_t addr){
  asm volatile("ldmatrix.sync.aligned.m8n8.x4.shared.b16 {%0,%1,%2,%3},[%4];"
    : "=r"(r[0]),"=r"(r[1]),"=r"(r[2]),"=r"(r[3]) : "r"(addr));
}
DEVFN void ldsm4t(uint32_t* r, uint32_t addr){
  asm volatile("ldmatrix.sync.aligned.m8n8.x4.trans.shared.b16 {%0,%1,%2,%3},[%4];"
    : "=r"(r[0]),"=r"(r[1]),"=r"(r[2]),"=r"(r[3]) : "r"(addr));
}
DEVFN void mma16816(float* d, const uint32_t* a, const uint32_t* b){
  asm volatile("mma.sync.aligned.m16n8k16.row.col.f32.f16.f16.f32 "
    "{%0,%1,%2,%3},{%4,%5,%6,%7},{%8,%9},{%0,%1,%2,%3};"
    : "+f"(d[0]),"+f"(d[1]),"+f"(d[2]),"+f"(d[3])
    : "r"(a[0]),"r"(a[1]),"r"(a[2]),"r"(a[3]), "r"(b[0]),"r"(b[1]));
}
DEVFN void cvst(char* smb, int offH, int offL, int r, int c, float4 v){
  float h0=f16rt(v.x), h1=f16rt(v.y), h2=f16rt(v.z), h3=f16rt(v.w);
  uint32_t o = swz(r, c);
  *(uint2*)(smb+offH+o) = make_uint2(pkh(h0,h1), pkh(h2,h3));
  *(uint2*)(smb+offL+o) = make_uint2(pkh(v.x-h0,v.y-h1), pkh(v.z-h2,v.w-h3));
}
DEVFN void cvstH(char* smb, int offH, int r, int c, float4 v){
  uint32_t o = swz(r, c);
  *(uint2*)(smb+offH+o) = make_uint2(pkh(f16rt(v.x),f16rt(v.y)), pkh(f16rt(v.z),f16rt(v.w)));
}

__global__ void __launch_bounds__(128,2)
attn_kernel(const float* __restrict__ qg, const float* __restrict__ kg,
            const float* __restrict__ vg, const float* __restrict__ sg,
            float* __restrict__ out)
{
  extern __shared__ char sm[];
  uint32_t sb = smem_u32(sm);
  int tid = threadIdx.x, wid = tid>>5, lane = tid&31;
  int x = blockIdx.x;
  int b = x&7, qt = (x>>3)&15, h = x>>7;
  int q0 = qt*64;

  // ---- stage Q (64 rows) into persistent smem hi/lo ----
  const float* Q = qg + (((size_t)b*NH + h)*NS + q0)*ND;
#pragma unroll
  for (int it=0; it<16; ++it){
    int j = tid + it*128; int r = j>>5, c = (j&31)*4;
    cvst(sm, SM_QH, SM_QL, r, c, *(const float4*)(Q + (size_t)r*ND + c));
  }

  float o[64];
#pragma unroll
  for (int i=0;i<64;++i) o[i]=0.f;
  float m0=-1e30f, m1=-1e30f, rs0=0.f, rs1=0.f;

  int rq = wid*16 + (lane>>2);              // q-tile-local row of c0/c1
  const float* Sg  = sg + (((size_t)b*NH + h)*NS + q0 + rq)*NS + 2*(lane&3);
  const float* S0g = sg + (((size_t)h)*NS + q0 + rq)*NS + 2*(lane&3);
  const float* Kg  = kg + (((size_t)b*NH + h)*NS)*ND;
  const float* Vg  = vg + (((size_t)b*NH + h)*NS)*ND;

  int brow = lane&7, bsub = lane>>3;
  int rowa = wid*16 + ((lane>>3)&1)*8 + (lane&7);   // A-frag ldmatrix row
  int cola = (lane>>4)*8;                           // A-frag ldmatrix col

  // prefetch first k-tile's scale lines into L2 (64 cols = 2 lines/row)
#pragma unroll
  for (int j=0; j<2; ++j){
    pref(Sg  + 32*j); pref(Sg  + 8*NS + 32*j);
    pref(S0g + 32*j); pref(S0g + 8*NS + 32*j);
  }

  for (int kt=0; kt<16; ++kt){              // 16 tiles of 64 keys
    __syncthreads();
    // ---- load K (hi/lo), V (hi) 64-key tiles into swizzled smem ----
    const float* K = Kg + (size_t)kt*64*ND;
    const float* V = Vg + (size_t)kt*64*ND;
#pragma unroll
    for (int it=0; it<16; ++it){
      int j = tid + it*128; int r = j>>5, c = (j&31)*4;
      cvst (sm, SM_KH, SM_KL, r, c, *(const float4*)(K + (size_t)r*ND + c));
      cvstH(sm, SM_VH,        r, c, *(const float4*)(V + (size_t)r*ND + c));
    }
    __syncthreads();

    // ---- S = Qhi*Khi + Qlo*Khi + Qhi*Klo over 64 keys ----
    float s[32];
#pragma unroll
    for (int i=0;i<32;++i) s[i]=0.f;
#pragma unroll
    for (int kc=0; kc<8; kc+=2){
      uint32_t qh0[4], ql0[4], qh1[4], ql1[4];
      uint32_t aoff0 = swz(rowa,  kc   *16 + cola);
      uint32_t aoff1 = swz(rowa, (kc+1)*16 + cola);
      ldsm4(qh0, sb + SM_QH + aoff0);
      ldsm4(ql0, sb + SM_QL + aoff0);
      ldsm4(qh1, sb + SM_QH + aoff1);
      ldsm4(ql1, sb + SM_QL + aoff1);
#pragma unroll
      for (int j=0; j<8; ++j){
        uint32_t bh[4], bl[4];
        uint32_t off = swz(8*j + brow, kc*16 + bsub*8);
        ldsm4(bh, sb + SM_KH + off);
        ldsm4(bl, sb + SM_KL + off);
        mma16816(&s[4*j], qh0, bh);
        mma16816(&s[4*j], ql0, bh);
        mma16816(&s[4*j], qh0, bl);
        mma16816(&s[4*j], qh1, bh+2);
        mma16816(&s[4*j], ql1, bh+2);
        mma16816(&s[4*j], qh1, bl+2);
      }
    }

    // ---- elementwise scale * rsqrt(scale0), online max ----
    const float* sA0 = Sg  + kt*64;
    const float* sB0 = S0g + kt*64;
    float mx0=-1e30f, mx1=-1e30f;
#pragma unroll
    for (int j=0; j<8; ++j){
      float2 a0 = *(const float2*)(sA0 + 8*j);
      float2 b0 = *(const float2*)(sB0 + 8*j);
      float2 a1 = *(const float2*)(sA0 + 8*NS + 8*j);
      float2 b1 = *(const float2*)(sB0 + 8*NS + 8*j);
      s[4*j+0] *= a0.x * rsqrtf(b0.x);
      s[4*j+1] *= a0.y * rsqrtf(b0.y);
      s[4*j+2] *= a1.x * rsqrtf(b1.x);
      s[4*j+3] *= a1.y * rsqrtf(b1.y);
      mx0 = fmaxf(mx0, fmaxf(s[4*j+0], s[4*j+1]));
      mx1 = fmaxf(mx1, fmaxf(s[4*j+2], s[4*j+3]));
    }
    // prefetch next tile's scale lines
    if (kt < 15){
      const float* nA = sA0 + 64;
      const float* nB = sB0 + 64;
#pragma unroll
      for (int j=0; j<2; ++j){
        pref(nA + 32*j); pref(nA + 8*NS + 32*j);
        pref(nB + 32*j); pref(nB + 8*NS + 32*j);
      }
    }

    // ---- online softmax update ----
    mx0 = fmaxf(mx0, __shfl_xor_sync(0xffffffffu, mx0, 1));
    mx0 = fmaxf(mx0, __shfl_xor_sync(0xffffffffu, mx0, 2));
    mx1 = fmaxf(mx1, __shfl_xor_sync(0xffffffffu, mx1, 1));
    mx1 = fmaxf(mx1, __shfl_xor_sync(0xffffffffu, mx1, 2));
    float nm0 = fmaxf(m0, mx0), nm1 = fmaxf(m1, mx1);
    float al0 = __expf(m0 - nm0), al1 = __expf(m1 - nm1);
    m0 = nm0; m1 = nm1;
    rs0 *= al0; rs1 *= al1;
#pragma unroll
    for (int j=0; j<16; ++j){
      o[4*j+0] *= al0; o[4*j+1] *= al0;
      o[4*j+2] *= al1; o[4*j+3] *= al1;
    }

    // ---- exp, pack P (fp16 single product for PV) ----
    uint32_t pah[4][4];
#pragma unroll
    for (int j=0; j<8; ++j){
      float p0 = __expf(s[4*j+0] - m0), p1 = __expf(s[4*j+1] - m0);
      float p2 = __expf(s[4*j+2] - m1), p3 = __expf(s[4*j+3] - m1);
      rs0 += p0 + p1; rs1 += p2 + p3;
      int kcl = j>>1, q = 2*(j&1);
      pah[kcl][q+0] = pkh(f16rt(p0), f16rt(p1));
      pah[kcl][q+1] = pkh(f16rt(p2), f16rt(p3));
    }

    // prefetch next K/V tile lines (128B granularity) during PV phase
    if (kt < 15){
      const float* Kn = K + 64*ND;
      const float* Vn = V + 64*ND;
#pragma unroll
      for (int it=0; it<4; ++it){
        int j = tid + it*128; int r = j>>3, c = (j&7)*16;
        pref(Kn + (size_t)r*ND + c);
        pref(Vn + (size_t)r*ND + c);
      }
    }

    // ---- O += P * Vhi (64 keys) ----
#pragma unroll
    for (int kcl=0; kcl<4; kcl+=2){
#pragma unroll
      for (int j2=0; j2<16; ++j2){
        uint32_t vh[4];
        uint32_t off = swz(kcl*16 + (lane&7) + (lane>>3)*8, 8*j2);
        ldsm4t(vh, sb + SM_VH + off);
        mma16816(&o[4*j2], pah[kcl],   vh);
        mma16816(&o[4*j2], pah[kcl+1], vh+2);
      }
    }
  }

  // ---- normalize and store ----
  rs0 += __shfl_xor_sync(0xffffffffu, rs0, 1);
  rs0 += __shfl_xor_sync(0xffffffffu, rs0, 2);
  rs1 += __shfl_xor_sync(0xffffffffu, rs1, 1);
  rs1 += __shfl_xor_sync(0xffffffffu, rs1, 2);
  float inv0 = 1.0f/rs0, inv1 = 1.0f/rs1;

  float* O0 = out + (((size_t)b*NH + h)*NS + q0 + rq)*ND + 2*(lane&3);
#pragma unroll
  for (int j2=0; j2<16; ++j2){
    float2 w0, w1;
    w0.x = o[4*j2+0]*inv0; w0.y = o[4*j2+1]*inv0;
    w1.x = o[4*j2+2]*inv1; w1.y = o[4*j2+3]*inv1;
    *(float2*)(O0 + 8*j2) = w0;
    *(float2*)(O0 + 8*ND + 8*j2) = w1;   // row rq+8
  }
}

extern "C" void kernel_launch(void* const* d_in, const int* in_sizes, int n_in,
                              void* d_out, int out_size)
{
  const float* q = (const float*)d_in[0];
  const float* k = (const float*)d_in[1];
  const float* v = (const float*)d_in[2];
  const float* s = (const float*)d_in[3];
  float* o = (float*)d_out;
  cudaFuncSetAttribute(attn_kernel, cudaFuncAttributeMaxDynamicSharedMemorySize, SMEM_TOTAL);
  attn_kernel<<<NB*NH*(NS/64), 128, SMEM_TOTAL>>>(q, k, v, s, o);
}

// round 15
// speedup vs baseline: 1.1380x; 1.1380x over previous
#include <cuda_runtime.h>
#include <cuda_fp16.h>
#include <stdint.h>

#define NB 8
#define NH 16
#define NS 1024
#define ND 128

// smem: QH,QL,KH,KL (32KB each) + VH double buffer (2x32KB) = 192KB
#define SM_QH 0
#define SM_QL 32768
#define SM_KH 65536
#define SM_KL 98304
#define SM_VH0 131072
#define SMEM_TOTAL 196608

#define DEVFN static __device__ __forceinline__

// pre-converted, pre-swizzled fp16 planes (32MB each)
#define PLANE_BYTES (NB*NH*NS*ND*2)
__device__ char gQH[PLANE_BYTES];
__device__ char gQL[PLANE_BYTES];
__device__ char gKH[PLANE_BYTES];
__device__ char gKL[PLANE_BYTES];
__device__ char gVH[PLANE_BYTES];

DEVFN uint32_t smem_u32(const void* p){
  uint32_t a;
  asm("{.reg .u64 t; cvta.to.shared.u64 t,%1; cvt.u32.u64 %0,t;}":"=r"(a):"l"(p));
  return a;
}
DEVFN uint32_t swz(int r, int c){
  return (uint32_t)(r*256 + ((((c>>3) ^ (r&7)) & 15) << 4) + (c&7)*2);
}
DEVFN float f16rt(float x){ return __half2float(__float2half_rn(x)); }
DEVFN uint32_t pkh(float lo, float hi){
  uint32_t r; asm("cvt.rn.f16x2.f32 %0,%1,%2;":"=r"(r):"f"(hi),"f"(lo)); return r;
}
DEVFN void pref(const void* p){ asm volatile("prefetch.global.L2 [%0];"::"l"(p)); }
DEVFN void ldsm4(uint32_t* r, uint32_t addr){
  asm volatile("ldmatrix.sync.aligned.m8n8.x4.shared.b16 {%0,%1,%2,%3},[%4];"
    : "=r"(r[0]),"=r"(r[1]),"=r"(r[2]),"=r"(r[3]) : "r"(addr));
}
DEVFN void ldsm4t(uint32_t* r, uint32_t addr){
  asm volatile("ldmatrix.sync.aligned.m8n8.x4.trans.shared.b16 {%0,%1,%2,%3},[%4];"
    : "=r"(r[0]),"=r"(r[1]),"=r"(r[2]),"=r"(r[3]) : "r"(addr));
}
DEVFN void mma16816(float* d, const uint32_t* a, const uint32_t* b){
  asm volatile("mma.sync.aligned.m16n8k16.row.col.f32.f16.f16.f32 "
    "{%0,%1,%2,%3},{%4,%5,%6,%7},{%8,%9},{%0,%1,%2,%3};"
    : "+f"(d[0]),"+f"(d[1]),"+f"(d[2]),"+f"(d[3])
    : "r"(a[0]),"r"(a[1]),"r"(a[2]),"r"(a[3]), "r"(b[0]),"r"(b[1]));
}
DEVFN void cpa16(uint32_t dst, const void* src){
  asm volatile("cp.async.cg.shared.global [%0],[%1],16;"::"r"(dst),"l"(src));
}
DEVFN void cpa_commit(){ asm volatile("cp.async.commit_group;":::"memory"); }
DEVFN void cpa_wait0(){ asm volatile("cp.async.wait_group 0;":::"memory"); }
// flat 32KB tile copy via cp.async (256 threads)
DEVFN void copy32k(uint32_t smdst, const char* g, int tid){
#pragma unroll
  for (int it=0; it<8; ++it){
    int j = tid + it*256;
    cpa16(smdst + (uint32_t)j*16, g + (size_t)j*16);
  }
}

// ---- prologue: convert fp32 -> pre-swizzled fp16 hi/lo planes ----
__global__ void __launch_bounds__(256,1)
prep_planes(const float* __restrict__ qg, const float* __restrict__ kg,
            const float* __restrict__ vg)
{
  int t = blockIdx.x, tid = threadIdx.x;      // t over 1024 tiles (bh*8+seg)
  size_t rowbase = (size_t)(t>>3)*NS + (size_t)(t&7)*128;
  size_t tb = (size_t)t << 15;                // 32KB per tile per plane
#pragma unroll
  for (int it=0; it<16; ++it){
    int j = tid + it*256; int r = j>>5, c = (j&31)*4;
    size_t off = (rowbase + r)*ND + c;
    uint32_t so = swz(r, c);
    float4 q = *(const float4*)(qg + off);
    float4 k = *(const float4*)(kg + off);
    float4 v = *(const float4*)(vg + off);
    float qh0=f16rt(q.x),qh1=f16rt(q.y),qh2=f16rt(q.z),qh3=f16rt(q.w);
    float kh0=f16rt(k.x),kh1=f16rt(k.y),kh2=f16rt(k.z),kh3=f16rt(k.w);
    *(uint2*)(gQH+tb+so) = make_uint2(pkh(qh0,qh1), pkh(qh2,qh3));
    *(uint2*)(gQL+tb+so) = make_uint2(pkh(q.x-qh0,q.y-qh1), pkh(q.z-qh2,q.w-qh3));
    *(uint2*)(gKH+tb+so) = make_uint2(pkh(kh0,kh1), pkh(kh2,kh3));
    *(uint2*)(gKL+tb+so) = make_uint2(pkh(k.x-kh0,k.y-kh1), pkh(k.z-kh2,k.w-kh3));
    *(uint2*)(gVH+tb+so) = make_uint2(pkh(f16rt(v.x),f16rt(v.y)), pkh(f16rt(v.z),f16rt(v.w)));
  }
}

__global__ void __launch_bounds__(256,1)
attn_kernel(const float* __restrict__ sg, float* __restrict__ out)
{
  extern __shared__ char sm[];
  uint32_t sb = smem_u32(sm);
  int tid = threadIdx.x, wid = tid>>5, lane = tid&31;
  int x = blockIdx.x;
  int b = x&7, qt = (x>>3)&7, h = x>>6;
  int q0 = qt*128;
  int bh8 = (b*NH + h)*8;

  // issue Q + first K/V tile copies
  copy32k(sb+SM_QH, gQH + ((size_t)(bh8+qt)<<15), tid);
  copy32k(sb+SM_QL, gQL + ((size_t)(bh8+qt)<<15), tid);
  copy32k(sb+SM_KH, gKH + ((size_t)bh8<<15), tid);
  copy32k(sb+SM_KL, gKL + ((size_t)bh8<<15), tid);
  copy32k(sb+SM_VH0, gVH + ((size_t)bh8<<15), tid);
  cpa_commit();

  float o[64];
#pragma unroll
  for (int i=0;i<64;++i) o[i]=0.f;
  float m0=-1e30f, m1=-1e30f, rs0=0.f, rs1=0.f;

  int rq = wid*16 + (lane>>2);
  const float* Sg  = sg + (((size_t)b*NH + h)*NS + q0 + rq)*NS + 2*(lane&3);
  const float* S0g = sg + (((size_t)h)*NS + q0 + rq)*NS + 2*(lane&3);

  int brow = lane&7, bsub = lane>>3;
  int rowa = wid*16 + ((lane>>3)&1)*8 + (lane&7);
  int cola = (lane>>4)*8;

  // prefetch first tile's scale lines into L2
#pragma unroll
  for (int j=0; j<4; ++j){
    pref(Sg  + 32*j); pref(Sg  + 8*NS + 32*j);
    pref(S0g + 32*j); pref(S0g + 8*NS + 32*j);
  }

  for (int kt=0; kt<8; ++kt){
    cpa_wait0();
    __syncthreads();
    uint32_t vb = sb + SM_VH0 + (uint32_t)(kt&1)*32768;

#pragma unroll
    for (int hf=0; hf<2; ++hf){
      // ---- S = Qhi*Khi + Qlo*Khi + Qhi*Klo for this 64-key half ----
      float s[32];
#pragma unroll
      for (int i=0;i<32;++i) s[i]=0.f;
#pragma unroll
      for (int kc=0; kc<8; kc+=2){
        uint32_t qh0[4], ql0[4], qh1[4], ql1[4];
        uint32_t aoff0 = swz(rowa,  kc   *16 + cola);
        uint32_t aoff1 = swz(rowa, (kc+1)*16 + cola);
        ldsm4(qh0, sb + SM_QH + aoff0);
        ldsm4(ql0, sb + SM_QL + aoff0);
        ldsm4(qh1, sb + SM_QH + aoff1);
        ldsm4(ql1, sb + SM_QL + aoff1);
#pragma unroll
        for (int j=0; j<8; ++j){
          uint32_t bh[4], bl[4];
          uint32_t off = swz(64*hf + 8*j + brow, kc*16 + bsub*8);
          ldsm4(bh, sb + SM_KH + off);
          ldsm4(bl, sb + SM_KL + off);
          mma16816(&s[4*j], qh0, bh);
          mma16816(&s[4*j], ql0, bh);
          mma16816(&s[4*j], qh0, bl);
          mma16816(&s[4*j], qh1, bh+2);
          mma16816(&s[4*j], ql1, bh+2);
          mma16816(&s[4*j], qh1, bl+2);
        }
      }

      // after the LAST use of K smem this tile: start next tile's copies
      if (hf==1){
        __syncthreads();              // all warps done reading KH/KL
        if (kt < 7){
          copy32k(sb+SM_KH, gKH + ((size_t)(bh8+kt+1)<<15), tid);
          copy32k(sb+SM_KL, gKL + ((size_t)(bh8+kt+1)<<15), tid);
          copy32k(sb+SM_VH0 + (uint32_t)((kt+1)&1)*32768,
                  gVH + ((size_t)(bh8+kt+1)<<15), tid);
          cpa_commit();
        }
      }

      // ---- elementwise scale * rsqrt(scale0), online max ----
      const float* sA0 = Sg  + kt*128 + hf*64;
      const float* sB0 = S0g + kt*128 + hf*64;
      float mx0=-1e30f, mx1=-1e30f;
#pragma unroll
      for (int j=0; j<8; ++j){
        float2 a0 = *(const float2*)(sA0 + 8*j);
        float2 b0 = *(const float2*)(sB0 + 8*j);
        float2 a1 = *(const float2*)(sA0 + 8*NS + 8*j);
        float2 b1 = *(const float2*)(sB0 + 8*NS + 8*j);
        s[4*j+0] *= a0.x * rsqrtf(b0.x);
        s[4*j+1] *= a0.y * rsqrtf(b0.y);
        s[4*j+2] *= a1.x * rsqrtf(b1.x);
        s[4*j+3] *= a1.y * rsqrtf(b1.y);
        mx0 = fmaxf(mx0, fmaxf(s[4*j+0], s[4*j+1]));
        mx1 = fmaxf(mx1, fmaxf(s[4*j+2], s[4*j+3]));
      }
      // prefetch next tile's scale lines once per tile
      if (hf==0 && kt<7){
        const float* nA = Sg  + kt*128 + 128;
        const float* nB = S0g + kt*128 + 128;
#pragma unroll
        for (int j=0; j<4; ++j){
          pref(nA + 32*j); pref(nA + 8*NS + 32*j);
          pref(nB + 32*j); pref(nB + 8*NS + 32*j);
        }
      }

      // ---- online softmax update ----
      mx0 = fmaxf(mx0, __shfl_xor_sync(0xffffffffu, mx0, 1));
      mx0 = fmaxf(mx0, __shfl_xor_sync(0xffffffffu, mx0, 2));
      mx1 = fmaxf(mx1, __shfl_xor_sync(0xffffffffu, mx1, 1));
      mx1 = fmaxf(mx1, __shfl_xor_sync(0xffffffffu, mx1, 2));
      float nm0 = fmaxf(m0, mx0), nm1 = fmaxf(m1, mx1);
      float al0 = __expf(m0 - nm0), al1 = __expf(m1 - nm1);
      m0 = nm0; m1 = nm1;
      rs0 *= al0; rs1 *= al1;
#pragma unroll
      for (int j=0; j<16; ++j){
        o[4*j+0] *= al0; o[4*j+1] *= al0;
        o[4*j+2] *= al1; o[4*j+3] *= al1;
      }

      // ---- exp, pack P (fp16 single product for PV) ----
      uint32_t pah[4][4];
#pragma unroll
      for (int j=0; j<8; ++j){
        float p0 = __expf(s[4*j+0] - m0), p1 = __expf(s[4*j+1] - m0);
        float p2 = __expf(s[4*j+2] - m1), p3 = __expf(s[4*j+3] - m1);
        rs0 += p0 + p1; rs1 += p2 + p3;
        int kcl = j>>1, q = 2*(j&1);
        pah[kcl][q+0] = pkh(f16rt(p0), f16rt(p1));
        pah[kcl][q+1] = pkh(f16rt(p2), f16rt(p3));
      }

      // ---- O += P * Vhi over this key half ----
#pragma unroll
      for (int kcl=0; kcl<4; kcl+=2){
        int kcg = hf*4 + kcl;
#pragma unroll
        for (int j2=0; j2<16; ++j2){
          uint32_t vh[4];
          uint32_t off = swz(kcg*16 + (lane&7) + (lane>>3)*8, 8*j2);
          ldsm4t(vh, vb + off);
          mma16816(&o[4*j2], pah[kcl],   vh);
          mma16816(&o[4*j2], pah[kcl+1], vh+2);
        }
      }
    }
  }

  // ---- normalize and store ----
  rs0 += __shfl_xor_sync(0xffffffffu, rs0, 1);
  rs0 += __shfl_xor_sync(0xffffffffu, rs0, 2);
  rs1 += __shfl_xor_sync(0xffffffffu, rs1, 1);
  rs1 += __shfl_xor_sync(0xffffffffu, rs1, 2);
  float inv0 = 1.0f/rs0, inv1 = 1.0f/rs1;

  float* O0 = out + (((size_t)b*NH + h)*NS + q0 + rq)*ND + 2*(lane&3);
#pragma unroll
  for (int j2=0; j2<16; ++j2){
    float2 w0, w1;
    w0.x = o[4*j2+0]*inv0; w0.y = o[4*j2+1]*inv0;
    w1.x = o[4*j2+2]*inv1; w1.y = o[4*j2+3]*inv1;
    *(float2*)(O0 + 8*j2) = w0;
    *(float2*)(O0 + 8*ND + 8*j2) = w1;   // row rq+8
  }
}

extern "C" void kernel_launch(void* const* d_in, const int* in_sizes, int n_in,
                              void* d_out, int out_size)
{
  const float* q = (const float*)d_in[0];
  const float* k = (const float*)d_in[1];
  const float* v = (const float*)d_in[2];
  const float* s = (const float*)d_in[3];
  float* o = (float*)d_out;
  prep_planes<<<NB*NH*(NS/128), 256>>>(q, k, v);
  cudaFuncSetAttribute(attn_kernel, cudaFuncAttributeMaxDynamicSharedMemorySize, SMEM_TOTAL);
  attn_kernel<<<NB*NH*(NS/128), 256, SMEM_TOTAL>>>(s, o);
}